// round 9
// baseline (speedup 1.0000x reference)
#include <cuda_runtime.h>

// Problem shape (fixed by dataset instance)
#define B_   8
#define H_   96
#define W_   320
#define HWp  (H_ * W_)            // 30720
#define NPIX (B_ * HWp)           // 245760
#define VOL_ELEMS (B_ * 45 * HWp) // 11059200
#define INTERVAL (4.0f / 7.0f)
#define G_VOL  960                // persistent vol block slots (x2 iterations = 1920)
#define G_DISP 240                // persistent disp block slots (x2 iterations = 480)

// Bilinear sample, bank-column smem (slot i at win[i*128]).
__device__ __forceinline__ float interp_left(const float* win, int base, int maxRel,
                                             float cand)
{
    float f = floorf(cand);
    float w = __fsub_rn(cand, f);
    int fi = (int)f - base;
    int bi = min(fi + 1, maxRel);
    float a = win[fi * 128];
    float b = win[bi * 128];
    return __fmaf_rn(w, __fsub_rn(b, a), a);
}
__device__ __forceinline__ float interp_right(const float* win, int base, int maxRel,
                                              float cand, float w1m1)
{
    float c = fminf(cand, w1m1);
    float f = floorf(c);
    float w = __fsub_rn(c, f);
    int fi = (int)f - base;
    int bi = min(fi + 1, maxRel);
    float a = win[fi * 128];
    float b = win[bi * 128];
    return __fmaf_rn(w, __fsub_rn(b, a), a);
}

struct Px { float c0, c1, c2; int J2lo, J2hi, J1lo, K0, idx; };

__device__ __forceinline__ Px mkpx(int idx, float d)
{
    Px q; q.idx = idx;
    float fx = (float)(idx % W_);
    q.c0 = fminf(fmaxf(__fsub_rn(fx, d), 0.0f), 319.0f);
    q.c1 = fminf(fmaxf(__fsub_rn(__fmul_rn(fx, 0.5f),  __fmul_rn(d, 0.5f)),  0.0f), 159.0f);
    q.c2 = fminf(fmaxf(__fsub_rn(__fmul_rn(fx, 0.25f), __fmul_rn(d, 0.25f)), 0.0f), 79.0f);
    q.J2lo = max(0, (int)floorf(q.c2) - 4);
    q.J2hi = min(79, (int)ceilf(q.c2) + 4);
    q.J1lo = max(0, (int)floorf(q.c1) - 4);
    q.K0   = max(0, (int)floorf(q.c0) - 4) >> 2;
    return q;
}

__global__ void __launch_bounds__(128, 7)
pcv_kernel(const float* __restrict__ corr,
           const float* __restrict__ disp,
           float* __restrict__ out)
{
    int bid = blockIdx.x;
    int t   = threadIdx.x;

    // ---- Disp-writer blocks (interleaved 1-in-5; persistent, 2 iterations) ----
    if (bid % 5 == 4) {
        int dp = bid / 5;                           // [0, G_DISP)
        #pragma unroll
        for (int k = 0; k < 2; ++k) {
            int g  = (dp + G_DISP * k) * 128 + t;   // quad index in [0, NPIX/4)
            int x4 = g % (W_ / 4);
            int bh = g / (W_ / 4);
            int x  = 4 * x4;
            float4 d4 = *reinterpret_cast<const float4*>(disp + bh * W_ + x);
            int b = bh / H_;
            int h = bh - b * H_;
            float* dst = out + VOL_ELEMS + ((size_t)(b * 45) * H_ + h) * W_ + x;
            #pragma unroll
            for (int lv = 0; lv < 3; ++lv) {
                float inv = (lv == 0) ? 1.0f : (lv == 1) ? 0.5f : 0.25f;
                float4 dl;
                dl.x = __fmul_rn(d4.x, inv); dl.y = __fmul_rn(d4.y, inv);
                dl.z = __fmul_rn(d4.z, inv); dl.w = __fmul_rn(d4.w, inv);
                #pragma unroll
                for (int c = 0; c < 15; ++c) {
                    float kk = __fmul_rn((float)(c - 7), INTERVAL);
                    float4 v;
                    v.x = __fadd_rn(kk, dl.x); v.y = __fadd_rn(kk, dl.y);
                    v.z = __fadd_rn(kk, dl.z); v.w = __fadd_rn(kk, dl.w);
                    *reinterpret_cast<float4*>(dst + (size_t)(lv * 15 + c) * HWp) = v;
                }
            }
        }
        return;
    }

    // ---- Vol blocks (persistent, software-pipelined over 2 pixels/thread) ----
    // Slot-major per-thread windows: element (slot, t) at [slot*128 + t].
    __shared__ float l0S[16 * 128];
    __shared__ float p1S[10 * 128];
    __shared__ float p2S[10 * 128];

    float* l0 = l0S + t;
    float* p1 = p1S + t;
    float* p2 = p2S + t;

    const float4* corr4 = reinterpret_cast<const float4*>(corr);

    int vbid = (bid / 5) * 4 + (bid % 5);           // [0, G_VOL)

    // Pipeline prologue: disp for both iterations, corr gather for iteration 0.
    int idx0 = vbid * 128 + t;
    float d0 = __ldg(disp + idx0);
    float dn = __ldg(disp + idx0 + G_VOL * 128);    // disp for k=1
    Px cur = mkpx(idx0, d0);

    float4 vv[10];
    {
        const float4* r4 = corr4 + (size_t)idx0 * (W_ / 4);
        int n4 = cur.J2hi - cur.J2lo;
        #pragma unroll
        for (int j = 0; j < 10; ++j)
            vv[j] = __ldcs(r4 + (cur.J2lo + min(j, n4)));
    }

    #pragma unroll
    for (int k = 0; k < 2; ++k) {
        // ---- Build windows for 'cur' from vv (consumes vv) ----
        #pragma unroll
        for (int jj = 0; jj < 10; ++jj) {
            float4 v = vv[jj];
            int q = cur.J2lo + jj - cur.K0;
            if ((unsigned)q < 4u) {
                l0[(4*q+0) * 128] = v.x; l0[(4*q+1) * 128] = v.y;
                l0[(4*q+2) * 128] = v.z; l0[(4*q+3) * 128] = v.w;
            }
            float s0 = __fmul_rn(__fadd_rn(v.x, v.y), 0.5f);
            float s1 = __fmul_rn(__fadd_rn(v.z, v.w), 0.5f);
            int slot = 2 * (cur.J2lo + jj) - cur.J1lo;
            if ((unsigned)slot       < 10u) p1[slot * 128]       = s0;
            if ((unsigned)(slot + 1) < 10u) p1[(slot + 1) * 128] = s1;
            p2[jj * 128] = __fmul_rn(__fadd_rn(s0, s1), 0.5f);
        }

        // ---- Prefetch next pixel: gather flies during this pixel's sampling ----
        Px nxt = cur;
        if (k == 0) {
            int idxn = cur.idx + G_VOL * 128;
            nxt = mkpx(idxn, dn);
            const float4* r4 = corr4 + (size_t)idxn * (W_ / 4);
            int m4 = nxt.J2hi - nxt.J2lo;
            #pragma unroll
            for (int j = 0; j < 10; ++j)
                vv[j] = __ldcs(r4 + (nxt.J2lo + min(j, m4)));
        }

        // ---- Sample 'cur' (LDS + STG) while next gather is in flight ----
        int x  = cur.idx % W_;
        int bh = cur.idx / W_;
        int b  = bh / H_;
        int h  = bh - b * H_;
        int volBase = (b * 45 * H_ + h) * W_ + x;
        float fx = (float)x;

        const float ctr[3]   = {cur.c0, cur.c1, cur.c2};
        const float w1m1a[3] = {319.0f, 159.0f, 79.0f};
        const int maxRelA[3] = { 4 * min(3, cur.J2lo + 9 - cur.K0) + 3,
                                 min(9, 2 * cur.J2hi + 1 - cur.J1lo),
                                 9 };

        #pragma unroll
        for (int lv = 0; lv < 3; ++lv) {
            const float* win = (lv == 0) ? l0 : (lv == 1) ? p1 : p2;
            int   base   = (lv == 0) ? 4 * cur.K0 : (lv == 1) ? cur.J1lo : cur.J2lo;
            int   maxRel = maxRelA[lv];
            float inv    = (lv == 0) ? 1.0f : (lv == 1) ? 0.5f : 0.25f;
            float center = ctr[lv];
            float w1m1   = w1m1a[lv];
            float stdv   = __fmul_rn(fx, inv);
            float cm4 = __fsub_rn(center, 4.0f);
            float cp4 = __fadd_rn(center, 4.0f);

            float* outL = out + volBase + lv * 15 * HWp;

            #pragma unroll
            for (int s = 0; s < 8; ++s) {
                float off = __fmul_rn((float)s, INTERVAL);
                float lc = __fadd_rn(cm4, off);
                float vl = 0.0f;
                if (lc > 0.0f) vl = interp_left(win, base, maxRel, lc);
                outL[s * HWp] = vl;
                if (s < 7) {
                    float rc = __fsub_rn(cp4, off);
                    float dnm = __fsub_rn(stdv, rc);
                    float vr = 0.0f;
                    if (dnm > 0.0f && dnm < w1m1)
                        vr = interp_right(win, base, maxRel, rc, w1m1);
                    outL[(14 - s) * HWp] = vr;
                }
            }
        }

        cur = nxt;
    }
}

extern "C" void kernel_launch(void* const* d_in, const int* in_sizes, int n_in,
                              void* d_out, int out_size)
{
    const float* corr = (const float*)d_in[0];   // cross_attention [8,96,320,320]
    const float* disp = (const float*)d_in[1];   // cur_disp [8,1,96,320]
    float* out = (float*)d_out;                  // [vol ; disps], each [8,45,96,320]
    pcv_kernel<<<G_VOL + G_DISP, 128>>>(corr, disp, out);
}

// round 10
// speedup vs baseline: 1.0633x; 1.0633x over previous
#include <cuda_runtime.h>

// Problem shape (fixed by dataset instance)
#define B_   8
#define H_   96
#define W_   320
#define HWp  (H_ * W_)            // 30720
#define NPIX (B_ * HWp)           // 245760
#define VOL_ELEMS (B_ * 45 * HWp) // 11059200
#define INTERVAL (4.0f / 7.0f)
#define NVOLB  1920               // vol blocks (NPIX/128)
#define NDISPB 480                // disp blocks (NPIX/4/128)

__global__ void __launch_bounds__(128, 8)
pcv_kernel(const float* __restrict__ corr,
           const float* __restrict__ disp,
           float* __restrict__ out)
{
    int bid = blockIdx.x;
    int t   = threadIdx.x;

    // ---- Disp-writer blocks (interleaved 1-in-5): closed-form, float4 stores ----
    if (bid % 5 == 4) {
        int g  = (bid / 5) * 128 + t;          // quad index in [0, NPIX/4)
        int x4 = g % (W_ / 4);
        int bh = g / (W_ / 4);
        int x  = 4 * x4;
        float4 d4 = *reinterpret_cast<const float4*>(disp + bh * W_ + x);
        int b = bh / H_;
        int h = bh - b * H_;
        float* dst = out + VOL_ELEMS + ((size_t)(b * 45) * H_ + h) * W_ + x;
        #pragma unroll
        for (int lv = 0; lv < 3; ++lv) {
            float inv = (lv == 0) ? 1.0f : (lv == 1) ? 0.5f : 0.25f;
            float4 dl;
            dl.x = __fmul_rn(d4.x, inv); dl.y = __fmul_rn(d4.y, inv);
            dl.z = __fmul_rn(d4.z, inv); dl.w = __fmul_rn(d4.w, inv);
            #pragma unroll
            for (int c = 0; c < 15; ++c) {
                float kk = __fmul_rn((float)(c - 7), INTERVAL);
                float4 v;
                v.x = __fadd_rn(kk, dl.x); v.y = __fadd_rn(kk, dl.y);
                v.z = __fadd_rn(kk, dl.z); v.w = __fadd_rn(kk, dl.w);
                *reinterpret_cast<float4*>(dst + (size_t)(lv * 15 + c) * HWp) = v;
            }
        }
        return;
    }

    // ---- Vol blocks ----
    // Slot-major per-thread windows: element (slot, t) at [slot*128 + t].
    __shared__ float l0S[16 * 128];
    __shared__ float p1S[10 * 128];
    __shared__ float p2S[10 * 128];

    int vbid = (bid / 5) * 4 + (bid % 5);       // [0, 1920)
    int idx  = vbid * 128 + t;

    int x  = idx % W_;
    int bh = idx / W_;
    float d  = __ldg(disp + idx);
    float fx = (float)x;

    const float4* row4 = reinterpret_cast<const float4*>(corr) + (size_t)idx * (W_ / 4);

    // centers per level: clip(x/2^i - d/2^i, 0, w1-1)
    float c0 = fminf(fmaxf(__fsub_rn(fx, d), 0.0f), 319.0f);
    float c1 = fminf(fmaxf(__fsub_rn(__fmul_rn(fx, 0.5f),  __fmul_rn(d, 0.5f)),  0.0f), 159.0f);
    float c2 = fminf(fmaxf(__fsub_rn(__fmul_rn(fx, 0.25f), __fmul_rn(d, 0.25f)), 0.0f), 79.0f);

    float F0 = floorf(c0), F1 = floorf(c1), F2 = floorf(c2);
    int iF0 = (int)F0, iF1 = (int)F1, iF2 = (int)F2;

    int J2lo = max(0, iF2 - 4);
    int J2hi = min(79, (int)ceilf(c2) + 4);
    int n4   = J2hi - J2lo;                       // 0..9
    int J1lo = max(0, iF1 - 4);
    int K0   = max(0, iF0 - 4) >> 2;

    float* l0 = l0S + t;
    float* p1 = p1S + t;
    float* p2 = p2S + t;

    // Gather (MLP=10, clamped address stays in-bounds) + scatter windows to smem.
    float4 vv[10];
    #pragma unroll
    for (int jj = 0; jj < 10; ++jj)
        vv[jj] = __ldcs(row4 + (J2lo + min(jj, n4)));

    #pragma unroll
    for (int jj = 0; jj < 10; ++jj) {
        float4 v = vv[jj];
        int q = J2lo + jj - K0;
        if ((unsigned)q < 4u) {
            l0[(4*q+0) * 128] = v.x; l0[(4*q+1) * 128] = v.y;
            l0[(4*q+2) * 128] = v.z; l0[(4*q+3) * 128] = v.w;
        }
        float s0 = __fmul_rn(__fadd_rn(v.x, v.y), 0.5f);
        float s1 = __fmul_rn(__fadd_rn(v.z, v.w), 0.5f);
        int slot = 2 * (J2lo + jj) - J1lo;
        if ((unsigned)slot       < 10u) p1[slot * 128]       = s0;
        if ((unsigned)(slot + 1) < 10u) p1[(slot + 1) * 128] = s1;
        p2[jj * 128] = __fmul_rn(__fadd_rn(s0, s1), 0.5f);
    }

    int b = bh / H_;
    int h = bh - b * H_;
    int volBase = (b * 45 * H_ + h) * W_ + x;

    // e_s = floor(s * 4/7) — compile-time
    const int EL[8] = {0, 0, 1, 1, 2, 2, 3, 4};

    const float ctr[3]   = {c0, c1, c2};
    const float Ffs[3]   = {F0, F1, F2};
    const float w1m1a[3] = {319.0f, 159.0f, 79.0f};
    const int   offA[3]  = { iF0 - 4 - 4 * K0, iF1 - 4 - J1lo, iF2 - 4 - J2lo };
    const int   top1     = min(9, 2 * J2hi + 1 - J1lo);

    #pragma unroll
    for (int lv = 0; lv < 3; ++lv) {
        const float* win = (lv == 0) ? l0 : (lv == 1) ? p1 : p2;
        int   off    = offA[lv];
        float Ff     = Ffs[lv];
        float center = ctr[lv];
        float w1m1   = w1m1a[lv];
        float inv    = (lv == 0) ? 1.0f : (lv == 1) ? 0.5f : 0.25f;

        // Register window: w[i] == level-window[F-4+i]; clamped slots are only
        // ever read with zero weight or by guarded-off samples (finite garbage).
        float w[10];
        #pragma unroll
        for (int i = 0; i < 10; ++i) {
            int s = max(off + i, 0);
            if (lv == 1) s = min(s, top1);
            w[i] = win[s * 128];
        }

        float fm4  = __fsub_rn(Ff, 4.0f);       // exact
        float cm4  = __fsub_rn(center, 4.0f);   // exact
        float cp4  = __fadd_rn(center, 4.0f);   // exact
        float stdv = __fmul_rn(fx, inv);

        float* outL = out + volBase + lv * 15 * HWp;

        #pragma unroll
        for (int s8 = 0; s8 < 8; ++s8) {
            const int e = EL[s8];
            float offs = __fmul_rn((float)s8, INTERVAL);

            // LEFT: floor(lc) in {F-4+e, F-4+e+1}; pick via exact float compare.
            float lc   = __fadd_rn(cm4, offs);
            float bnd0 = __fadd_rn(fm4, (float)e);        // integer-valued, exact
            float bnd1 = __fadd_rn(fm4, (float)(e + 1));
            bool  bl   = lc >= bnd1;
            float a    = bl ? w[e + 1] : w[e];
            float bb   = bl ? w[e + 2] : w[e + 1];
            float wt   = __fsub_rn(lc, bl ? bnd1 : bnd0); // exact (int subtrahend)
            float v    = __fmaf_rn(wt, __fsub_rn(bb, a), a);
            outL[s8 * HWp] = (lc > 0.0f) ? v : 0.0f;

            // RIGHT: sample s -> channel 14-s; floor(c) in {F+3-e, F+4-e}.
            if (s8 < 7) {
                float rc = __fsub_rn(cp4, offs);
                float dn = __fsub_rn(stdv, rc);
                float c  = fminf(rc, w1m1);
                float r0 = __fadd_rn(Ff, (float)(3 - e));
                float r1 = __fadd_rn(Ff, (float)(4 - e));
                bool  br = c >= r1;
                float ar  = br ? w[8 - e] : w[7 - e];
                float bbr = br ? w[9 - e] : w[8 - e];
                float wr  = __fsub_rn(c, br ? r1 : r0);
                float vr  = __fmaf_rn(wr, __fsub_rn(bbr, ar), ar);
                outL[(14 - s8) * HWp] = (dn > 0.0f && dn < w1m1) ? vr : 0.0f;
            }
        }
    }
}

extern "C" void kernel_launch(void* const* d_in, const int* in_sizes, int n_in,
                              void* d_out, int out_size)
{
    const float* corr = (const float*)d_in[0];   // cross_attention [8,96,320,320]
    const float* disp = (const float*)d_in[1];   // cur_disp [8,1,96,320]
    float* out = (float*)d_out;                  // [vol ; disps], each [8,45,96,320]
    pcv_kernel<<<NVOLB + NDISPB, 128>>>(corr, disp, out);
}